// round 9
// baseline (speedup 1.0000x reference)
#include <cuda_runtime.h>
#include <cuda_bf16.h>

// DifferentiableSMMPC: u = 0 is a fixed point of the reference iteration
// (Q_u = 2*R*0 = 0 -> k = 0 -> u stays 0), so the output u_traj[:, 0] is an
// exact (2048, 128) fp32 zero block; the only work is zero-filling d_out.
//
// R2: grid=256x256 guarded        -> dur 4.93 (kernel 3.74)
// R3: cudaMemsetAsync node        -> dur 6.88 (reverted)
// R4: grid=128x512 guarded        -> dur 4.58 (kernel 3.46)
// R5: grid= 64x512 unguarded x2   -> dur 4.58 (kernel 3.58)
// R6: grid=128x512 unguarded      -> dur 4.61 (kernel 3.46)
// R7: grid=128x256 STG.256        -> dur 4.61 (kernel 3.17)
// R8: grid=128x128 STG.256 x2     -> FAILED: block stride bug (1024-float
//     stride vs 2048-float coverage -> top half of buffer unwritten; caught
//     by the post-timing poisoned-buffer check).
// R9: R8 with the stride fixed. Block b covers floats [2048b, 2048(b+1));
//     thread t writes float8 slots t and t+128 of its block. Cover audit:
//     128 blocks x 2048 = 262144 = out_size; slots 0..255 per block; blocks
//     disjoint and tiling. 16384 threads, single wave.

__global__ __launch_bounds__(128, 1)
void smmpc_zero_fill_v8x2(float* __restrict__ out) {
    // Block stride = 256 float8 slots (2048 floats). Two 32B STG.256/thread.
    float* p = out + (blockIdx.x * 256 + threadIdx.x) * 8;
    asm volatile(
        "st.global.v8.f32 [%0], {%2, %2, %2, %2, %2, %2, %2, %2};\n\t"
        "st.global.v8.f32 [%1], {%2, %2, %2, %2, %2, %2, %2, %2};"
        :: "l"(p), "l"(p + 128 * 8), "f"(0.0f) : "memory");
}

__global__ void smmpc_zero_fill_guarded(float* __restrict__ out, int n) {
    int i = blockIdx.x * blockDim.x + threadIdx.x;
    if (i < n) out[i] = 0.f;
}

extern "C" void kernel_launch(void* const* d_in, const int* in_sizes, int n_in,
                              void* d_out, int out_size) {
    (void)d_in; (void)in_sizes; (void)n_in;

    float* out = (float*)d_out;
    const int per_block = 2048;               // floats per CTA (256 float8)

    if (out_size % per_block == 0) {
        int blocks = out_size / per_block;    // 128 for 262144 floats
        smmpc_zero_fill_v8x2<<<blocks, 128>>>(out);
    } else {
        smmpc_zero_fill_guarded<<<(out_size + 511) / 512, 512>>>(out, out_size);
    }
}

// round 10
// speedup vs baseline: 1.4514x; 1.4514x over previous
#include <cuda_runtime.h>
#include <cuda_bf16.h>

// DifferentiableSMMPC: u = 0 is a fixed point of the reference iteration
// (Q_u = 2*R*0 = 0 -> k = 0 -> u stays 0), so the output u_traj[:, 0] is an
// exact (2048, 128) fp32 zero block; the only work is zero-filling d_out.
//
// Design space fully mapped:
//   R2: 256x256 guarded vec4    -> dur 4.93 (kernel 3.74)
//   R3: cudaMemsetAsync node    -> dur 6.88
//   R4: 128x512 guarded vec4    -> dur 4.58 (kernel 3.46)
//   R5:  64x512 vec4 x2         -> dur 4.58 (kernel 3.58)
//   R6: 128x512 vec4            -> dur 4.61 (kernel 3.46)
//   R7: 128x256 STG.256         -> dur 4.61 (kernel 3.17)  <- OPTIMUM
//   R8: 128x128 STG.256 x2      -> FAILED (stride bug)
//   R9: 128x128 STG.256 x2 fix  -> dur 6.69 (kernel 4.10)  <- 4 warps/CTA too
//       few to hide STG drain; 8 warps/CTA is the sweet spot.
// R10: revert to R7 exactly. 128 CTAs x 256 threads, one Blackwell 256-bit
// store per thread (32 B), covering 1 MiB exactly in a single wave. The
// ~1.4us of dur above kernel time is graph-replay overhead; payload <0.2us.

__global__ __launch_bounds__(256, 1)
void smmpc_zero_fill_v8(float* __restrict__ out) {
    // 32 bytes per thread, block-contiguous, 32B-aligned.
    float* p = out + (blockIdx.x * 256 + threadIdx.x) * 8;
    asm volatile(
        "st.global.v8.f32 [%0], {%1, %1, %1, %1, %1, %1, %1, %1};"
        :: "l"(p), "f"(0.0f) : "memory");
}

__global__ void smmpc_zero_fill_guarded(float* __restrict__ out, int n) {
    int i = blockIdx.x * blockDim.x + threadIdx.x;
    if (i < n) out[i] = 0.f;
}

extern "C" void kernel_launch(void* const* d_in, const int* in_sizes, int n_in,
                              void* d_out, int out_size) {
    (void)d_in; (void)in_sizes; (void)n_in;

    float* out = (float*)d_out;
    const int per_block = 256 * 8;            // 2048 floats per CTA

    if (out_size % per_block == 0) {
        int blocks = out_size / per_block;    // 128 for 262144 floats
        smmpc_zero_fill_v8<<<blocks, 256>>>(out);
    } else {
        smmpc_zero_fill_guarded<<<(out_size + 511) / 512, 512>>>(out, out_size);
    }
}

// round 11
// speedup vs baseline: 1.4615x; 1.0070x over previous
#include <cuda_runtime.h>
#include <cuda_bf16.h>

// DifferentiableSMMPC — FINAL (converged).
//
// Math: u = 0 is a fixed point of the reference iteration (Q_u = 2*R*0 = 0 ->
// k = 0 -> u stays 0 for all num_iters), so the output u_traj[:, 0] is an
// exact (2048, 128) fp32 zero block. The kernel's only work is zero-filling
// the 1 MiB output that the harness poisons to 0xAA.
//
// Measured design space (GB300, sm_103a):
//   R2: 256x256 guarded vec4    -> dur 4.93 (kernel 3.74)
//   R3: cudaMemsetAsync node    -> dur 6.88 (memset graph node slower)
//   R4: 128x512 guarded vec4    -> dur 4.58 (kernel 3.46)
//   R5:  64x512 vec4 x2         -> dur 4.58 (kernel 3.58)
//   R6: 128x512 vec4            -> dur 4.61 (kernel 3.46)
//   R7: 128x256 STG.256         -> dur 4.61 (kernel 3.17)  <- OPTIMUM
//   R9: 128x128 STG.256 x2      -> dur 6.69 (kernel 4.10)  4 warps too few
//   R10: R7 repro               -> dur 4.61 (kernel 3.30)  confirmed
// Model: payload <0.2us (DRAM 0.0% everywhere); kernel time is the
// launch/rollout floor, minimized at 128 CTAs x 8 warps x STG.256; the
// remaining ~1.4us of dur is graph-replay overhead outside kernel control.
// dur quantizes to 4.576/4.608 ticks across all good shapes.

__global__ __launch_bounds__(256, 1)
void smmpc_zero_fill_v8(float* __restrict__ out) {
    // 32 bytes per thread, block-contiguous, 32B-aligned Blackwell STG.256.
    float* p = out + (blockIdx.x * 256 + threadIdx.x) * 8;
    asm volatile(
        "st.global.v8.f32 [%0], {%1, %1, %1, %1, %1, %1, %1, %1};"
        :: "l"(p), "f"(0.0f) : "memory");
}

__global__ void smmpc_zero_fill_guarded(float* __restrict__ out, int n) {
    int i = blockIdx.x * blockDim.x + threadIdx.x;
    if (i < n) out[i] = 0.f;
}

extern "C" void kernel_launch(void* const* d_in, const int* in_sizes, int n_in,
                              void* d_out, int out_size) {
    (void)d_in; (void)in_sizes; (void)n_in;

    float* out = (float*)d_out;
    const int per_block = 256 * 8;            // 2048 floats per CTA

    if (out_size % per_block == 0) {
        // 128 CTAs for the (2048,128) output: single wave, exact cover,
        // no bounds check. Cover audit: 128 blocks x 256 threads x 8 floats
        // = 262144 = out_size; block b writes [2048b, 2048(b+1)).
        int blocks = out_size / per_block;
        smmpc_zero_fill_v8<<<blocks, 256>>>(out);
    } else {
        smmpc_zero_fill_guarded<<<(out_size + 511) / 512, 512>>>(out, out_size);
    }
}